// round 4
// baseline (speedup 1.0000x reference)
#include <cuda_runtime.h>
#include <math.h>
#include <stdint.h>

// ---------------------------------------------------------------------------
// Problem constants
//   inputs [2048, 84, 84, 4] NHWC fp32
//   conv 3x3 s2 SAME x4 (ELU), channels 4->32->32->32->32
//   84 -> 42 -> 21 -> 11 -> 6   (FEAT = 6*6*32 = 1152)
//   LSTM size 256 over TL=64 steps, NT=32 trajectories, forget_bias=1
//   FC 256 -> 18
// ---------------------------------------------------------------------------

#define NIMG   2048
#define NT     32
#define TL     64
#define FEAT   1152
#define HID    256
#define NOUT   18

// ------------------------- device scratch (no cudaMalloc allowed) ----------
__device__ float g_c1[(size_t)NIMG * 42 * 42 * 32];   // 462 MB
__device__ float g_c2[(size_t)NIMG * 21 * 21 * 32];   // 116 MB
__device__ float g_c3[(size_t)NIMG * 11 * 11 * 32];   //  32 MB
__device__ float g_c4[(size_t)NIMG * 6 * 6 * 32];     //   9 MB
__device__ float g_xg[(size_t)NIMG * 1024];           //   8 MB  x@Wx + b
__device__ float g_whr[HID * HID * 4];                //   1 MB  Wh interleaved

// ---------------------------------------------------------------------------
// Wh reorder: whr[(k*256 + t)*4 + g] = lstm_w[(1152+k)*1024 + g*256 + t]
// so a thread owning hidden index t loads its 4 gate weights as one float4.
// ---------------------------------------------------------------------------
__global__ void reorder_wh_k(const float* __restrict__ lw, float* __restrict__ whr)
{
    const int k = blockIdx.x;     // 0..255  (h input dim)
    const int t = threadIdx.x;    // 0..255  (hidden index)
    const float* row = lw + (size_t)(FEAT + k) * 1024;
    float4 v;
    v.x = row[t];          // i
    v.y = row[256 + t];    // j
    v.z = row[512 + t];    // f
    v.w = row[768 + t];    // o
    *(float4*)(whr + ((size_t)k * 256 + t) * 4) = v;
}

// ---------------------------------------------------------------------------
// conv1: Cin=4 -> Cout=32, in 84x84, out 42x42, pad_begin=0
// block (32 co, 6 ox-tiles of 8), grid (42 oy, 512 n-groups of 4)
// ---------------------------------------------------------------------------
__global__ void conv1_k(const float* __restrict__ in, const float* __restrict__ w,
                        const float* __restrict__ bias, float* __restrict__ out)
{
    __shared__ float sw[9 * 4 * 32];          // [kpos][ci][co]
    const int co   = threadIdx.x;             // 32
    const int tile = threadIdx.y;             // 0..5
    const int oy   = blockIdx.x;              // 0..41
    const int n0   = blockIdx.y * 4;

    for (int i = tile * 32 + co; i < 9 * 4 * 32; i += 192) sw[i] = w[i];
    __syncthreads();

    const float bv  = bias[co];
    const int   ox0 = tile * 8;

    for (int img = 0; img < 4; img++) {
        const int n = n0 + img;
        float acc[8];
#pragma unroll
        for (int i = 0; i < 8; i++) acc[i] = bv;

        for (int ky = 0; ky < 3; ky++) {
            const int iy = oy * 2 + ky;
            if (iy >= 84) continue;
            const float* inr = in + ((size_t)(n * 84 + iy) * 84) * 4;
            for (int kx = 0; kx < 3; kx++) {
                const float* swk = sw + ((ky * 3 + kx) * 4) * 32 + co;
                const float w0 = swk[0], w1 = swk[32], w2 = swk[64], w3 = swk[96];
#pragma unroll
                for (int i = 0; i < 8; i++) {
                    const int ix = (ox0 + i) * 2 + kx;
                    if (ix < 84) {
                        const float4 x = *(const float4*)(inr + (size_t)ix * 4);
                        acc[i] += x.x * w0 + x.y * w1 + x.z * w2 + x.w * w3;
                    }
                }
            }
        }
        float* outr = out + ((size_t)(n * 42 + oy) * 42) * 32;
#pragma unroll
        for (int i = 0; i < 8; i++) {
            const int ox = ox0 + i;
            if (ox < 42) {
                float v = acc[i];
                outr[(size_t)ox * 32 + co] = (v > 0.f) ? v : (expf(v) - 1.f);
            }
        }
    }
}

// ---------------------------------------------------------------------------
// convN: Cin=32 -> Cout=32 direct conv + ELU
// block (32 co, ROWS*TPR): TPR ox-tiles of 8 per row, ROWS output rows.
// grid (ceil(OH/ROWS), NIMG/4). 4 images per block share the 36 KB weight smem.
// ---------------------------------------------------------------------------
template <int IH, int IW, int OH, int OW, int PAD, int ROWS, int TPR>
__global__ void convc32_k(const float* __restrict__ in, const float* __restrict__ w,
                          const float* __restrict__ bias, float* __restrict__ out)
{
    __shared__ float sw[9 * 32 * 32];         // [kpos][ci][co] = 36 KB
    const int co  = threadIdx.x;              // 32
    const int ty  = threadIdx.y;              // ROWS*TPR
    const int nth = 32 * ROWS * TPR;

    for (int i = ty * 32 + co; i < 9 * 32 * 32; i += nth) sw[i] = w[i];
    __syncthreads();

    const int tile = ty % TPR;
    const int ry   = ty / TPR;
    const int oy   = blockIdx.x * ROWS + ry;
    const int n0   = blockIdx.y * 4;
    const float bv = bias[co];
    const int ox0  = tile * 8;

    if (oy >= OH) return;

    for (int img = 0; img < 4; img++) {
        const int n = n0 + img;
        float acc[8];
#pragma unroll
        for (int i = 0; i < 8; i++) acc[i] = bv;

        for (int ky = 0; ky < 3; ky++) {
            const int iy = oy * 2 + ky - PAD;
            if (iy < 0 || iy >= IH) continue;
            const float* inr = in + ((size_t)(n * IH + iy) * IW) * 32;
            for (int kx = 0; kx < 3; kx++) {
                const float* swk = sw + ((ky * 3 + kx) * 32) * 32 + co;
#pragma unroll
                for (int c4 = 0; c4 < 32; c4 += 4) {
                    const float w0 = swk[(c4 + 0) * 32];
                    const float w1 = swk[(c4 + 1) * 32];
                    const float w2 = swk[(c4 + 2) * 32];
                    const float w3 = swk[(c4 + 3) * 32];
#pragma unroll
                    for (int i = 0; i < 8; i++) {
                        const int ix = (ox0 + i) * 2 + kx - PAD;
                        if (ix >= 0 && ix < IW) {
                            const float4 x = *(const float4*)(inr + (size_t)ix * 32 + c4);
                            acc[i] += x.x * w0 + x.y * w1 + x.z * w2 + x.w * w3;
                        }
                    }
                }
            }
        }
        float* outr = out + ((size_t)(n * OH + oy) * OW) * 32;
#pragma unroll
        for (int i = 0; i < 8; i++) {
            const int ox = ox0 + i;
            if (ox < OW) {
                float v = acc[i];
                outr[(size_t)ox * 32 + co] = (v > 0.f) ? v : (expf(v) - 1.f);
            }
        }
    }
}

// ---------------------------------------------------------------------------
// SGEMM: xg[2048,1024] = c4[2048,1152] @ lstm_w[0:1152, 0:1024] + lstm_b
// classic 128x128x8 tiling, 256 threads, 8x8 register micro-tile
// ---------------------------------------------------------------------------
__global__ void __launch_bounds__(256)
sgemm_xg_k(const float* __restrict__ A, const float* __restrict__ B,
           const float* __restrict__ bias, float* __restrict__ C)
{
    __shared__ float As[8][128];
    __shared__ float Bs[8][128];
    const int bx  = blockIdx.x;   // 0..7   (N tiles)
    const int by  = blockIdx.y;   // 0..15  (M tiles)
    const int tid = threadIdx.x;
    const int tr  = (tid / 16) * 8;
    const int tc  = (tid % 16) * 8;

    float acc[8][8];
#pragma unroll
    for (int i = 0; i < 8; i++)
#pragma unroll
        for (int j = 0; j < 8; j++) acc[i][j] = 0.f;

    const int ar = tid >> 1,  ac = (tid & 1) * 4;
    const int br = tid >> 5,  bc = (tid & 31) * 4;
    const float* Aptr = A + (size_t)(by * 128 + ar) * FEAT + ac;
    const float* Bptr = B + (size_t)br * 1024 + bx * 128 + bc;

    for (int k0 = 0; k0 < FEAT; k0 += 8) {
        const float4 av = *(const float4*)(Aptr + k0);
        As[ac + 0][ar] = av.x; As[ac + 1][ar] = av.y;
        As[ac + 2][ar] = av.z; As[ac + 3][ar] = av.w;
        *(float4*)&Bs[br][bc] = *(const float4*)(Bptr + (size_t)k0 * 1024);
        __syncthreads();
#pragma unroll
        for (int kk = 0; kk < 8; kk++) {
            float a[8], b[8];
#pragma unroll
            for (int i = 0; i < 8; i++) a[i] = As[kk][tr + i];
#pragma unroll
            for (int j = 0; j < 8; j++) b[j] = Bs[kk][tc + j];
#pragma unroll
            for (int i = 0; i < 8; i++)
#pragma unroll
                for (int j = 0; j < 8; j++) acc[i][j] += a[i] * b[j];
        }
        __syncthreads();
    }

#pragma unroll
    for (int i = 0; i < 8; i++) {
        const int row = by * 128 + tr + i;
        float* crow = C + (size_t)row * 1024 + bx * 128 + tc;
#pragma unroll
        for (int j = 0; j < 8; j += 4) {
            float4 v;
            v.x = acc[i][j + 0] + bias[bx * 128 + tc + j + 0];
            v.y = acc[i][j + 1] + bias[bx * 128 + tc + j + 1];
            v.z = acc[i][j + 2] + bias[bx * 128 + tc + j + 2];
            v.w = acc[i][j + 3] + bias[bx * 128 + tc + j + 3];
            *(float4*)(crow + j) = v;
        }
    }
}

// ---------------------------------------------------------------------------
// Fused LSTM recurrence + FC. One persistent block per trajectory (32 blocks),
// 256 threads = hidden size. Thread t owns c[t] in a register and computes
// gates (i,j,f,o)[t] directly (Wh pre-interleaved as float4 per (k,t)).
// h lives in SMEM; the 18-col FC head is computed by warps 0..5 each step and
// written straight to d_out.
// ---------------------------------------------------------------------------
__device__ __forceinline__ float sigmoidf_(float x) { return 1.f / (1.f + expf(-x)); }

__global__ void __launch_bounds__(256)
lstm_fused_k(const float* __restrict__ xg, const float* __restrict__ whr,
             const float* __restrict__ fcw, const float* __restrict__ fcb,
             const float* __restrict__ c0, const float* __restrict__ h0,
             float* __restrict__ out)
{
    const int n   = blockIdx.x;    // trajectory
    const int tid = threadIdx.x;   // hidden index
    __shared__ float sh[HID];

    float c = c0[(size_t)n * HID + tid];
    sh[tid] = h0[(size_t)n * HID + tid];
    __syncthreads();

    const int wrp = tid >> 5, lane = tid & 31;

    for (int t = 0; t < TL; t++) {
        const float* xrow = xg + (size_t)(n * TL + t) * 1024;
        float gi = xrow[tid];
        float gj = xrow[256 + tid];
        float gf = xrow[512 + tid];
        float go = xrow[768 + tid];

#pragma unroll 4
        for (int k = 0; k < HID; k++) {
            const float  hk = sh[k];
            const float4 w  = *(const float4*)(whr + ((size_t)k * HID + tid) * 4);
            gi += hk * w.x;
            gj += hk * w.y;
            gf += hk * w.z;
            go += hk * w.w;
        }

        const float nc = c * sigmoidf_(gf + 1.f) + sigmoidf_(gi) * tanhf(gj);
        const float nh = tanhf(nc) * sigmoidf_(go);
        c = nc;

        __syncthreads();
        sh[tid] = nh;
        __syncthreads();

        // FC head: 18 columns, warps 0..5 take 3 columns each
        if (wrp < 6) {
#pragma unroll
            for (int cc = 0; cc < 3; cc++) {
                const int col = wrp * 3 + cc;
                float s = 0.f;
#pragma unroll
                for (int k = lane; k < HID; k += 32) s += sh[k] * fcw[(size_t)k * NOUT + col];
#pragma unroll
                for (int off = 16; off; off >>= 1) s += __shfl_down_sync(0xffffffffu, s, off);
                if (lane == 0)
                    out[(size_t)(n * TL + t) * NOUT + col] = s + fcb[col];
            }
        }
    }
}

// ---------------------------------------------------------------------------
// Launch
// ---------------------------------------------------------------------------
extern "C" void kernel_launch(void* const* d_in, const int* in_sizes, int n_in,
                              void* d_out, int out_size)
{
    (void)in_sizes; (void)n_in; (void)out_size;
    const float* inp = (const float*)d_in[0];
    const float* w1  = (const float*)d_in[1];
    const float* b1  = (const float*)d_in[2];
    const float* w2  = (const float*)d_in[3];
    const float* b2  = (const float*)d_in[4];
    const float* w3  = (const float*)d_in[5];
    const float* b3  = (const float*)d_in[6];
    const float* w4  = (const float*)d_in[7];
    const float* b4  = (const float*)d_in[8];
    const float* lw  = (const float*)d_in[9];
    const float* lb  = (const float*)d_in[10];
    const float* fw  = (const float*)d_in[11];
    const float* fb  = (const float*)d_in[12];
    const float* c0  = (const float*)d_in[13];
    const float* h0  = (const float*)d_in[14];
    float* out = (float*)d_out;

    float *c1, *c2, *c3, *c4, *xg, *whr;
    cudaGetSymbolAddress((void**)&c1,  g_c1);
    cudaGetSymbolAddress((void**)&c2,  g_c2);
    cudaGetSymbolAddress((void**)&c3,  g_c3);
    cudaGetSymbolAddress((void**)&c4,  g_c4);
    cudaGetSymbolAddress((void**)&xg,  g_xg);
    cudaGetSymbolAddress((void**)&whr, g_whr);

    // Wh reorder (independent of conv chain)
    reorder_wh_k<<<256, 256>>>(lw, whr);

    // conv stack
    conv1_k<<<dim3(42, NIMG / 4), dim3(32, 6)>>>(inp, w1, b1, c1);
    convc32_k<42, 42, 21, 21, 0, 2, 3><<<dim3(11, NIMG / 4), dim3(32, 6)>>>(c1, w2, b2, c2);
    convc32_k<21, 21, 11, 11, 1, 3, 2><<<dim3(4,  NIMG / 4), dim3(32, 6)>>>(c2, w3, b3, c3);
    convc32_k<11, 11,  6,  6, 1, 6, 1><<<dim3(1,  NIMG / 4), dim3(32, 6)>>>(c3, w4, b4, c4);

    // time-parallel part of the LSTM input GEMM (+ bias)
    sgemm_xg_k<<<dim3(8, 16), 256>>>(c4, lw, lb, xg);

    // recurrence + FC head fused, one persistent block per trajectory
    lstm_fused_k<<<NT, HID>>>(xg, whr, fw, fb, c0, h0, out);
}

// round 5
// speedup vs baseline: 1.0622x; 1.0622x over previous
#include <cuda_runtime.h>
#include <math.h>
#include <stdint.h>

// ---------------------------------------------------------------------------
// Problem constants
//   inputs [2048, 84, 84, 4] NHWC fp32
//   conv 3x3 s2 SAME x4 (ELU), channels 4->32->32->32->32
//   84 -> 42 -> 21 -> 11 -> 6   (FEAT = 6*6*32 = 1152)
//   LSTM size 256 over TL=64 steps, NT=32 trajectories, forget_bias=1
//   FC 256 -> 18
// ---------------------------------------------------------------------------

#define NIMG   2048
#define NT     32
#define TL     64
#define FEAT   1152
#define HID    256
#define NOUT   18

// ------------------------- device scratch (no cudaMalloc allowed) ----------
__device__ float g_c1[(size_t)NIMG * 42 * 42 * 32];   // 462 MB
__device__ float g_c2[(size_t)NIMG * 21 * 21 * 32];   // 116 MB
__device__ float g_c3[(size_t)NIMG * 11 * 11 * 32];   //  32 MB
__device__ float g_c4[(size_t)NIMG * 6 * 6 * 32];     //   9 MB
__device__ float g_xg[(size_t)NIMG * 1024];           //   8 MB  x@Wx + b
__device__ float g_whr[HID * HID * 4];                //   1 MB  Wh interleaved

// ---------------------------------------------------------------------------
// Wh reorder: whr[(k*256 + t)*4 + g] = lstm_w[(1152+k)*1024 + g*256 + t]
// ---------------------------------------------------------------------------
__global__ void reorder_wh_k(const float* __restrict__ lw, float* __restrict__ whr)
{
    const int k = blockIdx.x;     // 0..255  (h input dim)
    const int t = threadIdx.x;    // 0..255  (hidden index)
    const float* row = lw + (size_t)(FEAT + k) * 1024;
    float4 v;
    v.x = row[t];          // i
    v.y = row[256 + t];    // j
    v.z = row[512 + t];    // f
    v.w = row[768 + t];    // o
    *(float4*)(whr + ((size_t)k * 256 + t) * 4) = v;
}

__device__ __forceinline__ float elu_(float v) { return v > 0.f ? v : (expf(v) - 1.f); }

// ---------------------------------------------------------------------------
// conv1 v2: Cin=4 -> Cout=32, 84x84 -> 42x42, pad_begin=0 (SAME pads at end)
// Each thread computes TOX ox-pixels x 4 consecutive co.
// One float4 input load (all 4 ci of a pixel) feeds 16 FMAs.
// block = 8 co-groups * OXT * ROWS threads; 4 images per block.
// ---------------------------------------------------------------------------
template <int TOX, int OXT, int ROWS>
__global__ void conv1_v2(const float* __restrict__ in, const float* __restrict__ w,
                         const float* __restrict__ bias, float* __restrict__ out)
{
    __shared__ float sw[9 * 4 * 32];              // [kpos][ci][co]
    const int tid = threadIdx.x;
    const int NTH = 8 * OXT * ROWS;
    for (int i = tid * 4; i < 9 * 4 * 32; i += NTH * 4)
        *(float4*)(sw + i) = *(const float4*)(w + i);
    __syncthreads();

    const int cg  = tid & 7;
    const int oxg = (tid >> 3) % OXT;
    const int ry  = (tid >> 3) / OXT;
    const int co0 = cg * 4;
    const int ox0 = oxg * TOX;
    const int oy  = blockIdx.x * ROWS + ry;
    const int n0  = blockIdx.y * 4;
    if (oy >= 42) return;

    const float4 bv = *(const float4*)(bias + co0);

#pragma unroll 1
    for (int img = 0; img < 4; img++) {
        const int n = n0 + img;
        float acc[TOX][4];
#pragma unroll
        for (int i = 0; i < TOX; i++) {
            acc[i][0] = bv.x; acc[i][1] = bv.y; acc[i][2] = bv.z; acc[i][3] = bv.w;
        }

#pragma unroll 1
        for (int ky = 0; ky < 3; ky++) {
            const int iy = oy * 2 + ky;
            if (iy >= 84) continue;
            const float* inr = in + ((size_t)(n * 84 + iy) * 84) * 4;
#pragma unroll 1
            for (int kx = 0; kx < 3; kx++) {
                const float* swk = sw + ((ky * 3 + kx) * 4) * 32 + co0;
                const float4 w0 = *(const float4*)(swk);
                const float4 w1 = *(const float4*)(swk + 32);
                const float4 w2 = *(const float4*)(swk + 64);
                const float4 w3 = *(const float4*)(swk + 96);
#pragma unroll
                for (int i = 0; i < TOX; i++) {
                    const int ix = (ox0 + i) * 2 + kx;
                    if (ix < 84) {
                        const float4 x = *(const float4*)(inr + (size_t)ix * 4);
                        acc[i][0] += x.x * w0.x + x.y * w1.x + x.z * w2.x + x.w * w3.x;
                        acc[i][1] += x.x * w0.y + x.y * w1.y + x.z * w2.y + x.w * w3.y;
                        acc[i][2] += x.x * w0.z + x.y * w1.z + x.z * w2.z + x.w * w3.z;
                        acc[i][3] += x.x * w0.w + x.y * w1.w + x.z * w2.w + x.w * w3.w;
                    }
                }
            }
        }
        float* outr = out + ((size_t)(n * 42 + oy) * 42) * 32 + co0;
#pragma unroll
        for (int i = 0; i < TOX; i++) {
            const int ox = ox0 + i;
            if (ox < 42) {
                float4 v;
                v.x = elu_(acc[i][0]); v.y = elu_(acc[i][1]);
                v.z = elu_(acc[i][2]); v.w = elu_(acc[i][3]);
                *(float4*)(outr + (size_t)ox * 32) = v;
            }
        }
    }
}

// ---------------------------------------------------------------------------
// convN v2: Cin=32 -> Cout=32 direct conv + ELU.
// Each thread: TOX ox-pixels x 4 consecutive co. Per (kpos, ci-quad):
//   4 weight float4 (LDS.128, reused over TOX) + TOX input float4 -> 16*TOX FMA.
// block = 8 co-groups * OXT * ROWS threads; 4 images per block share 36KB smem.
// ---------------------------------------------------------------------------
template <int IH, int IW, int OH, int OW, int PAD, int TOX, int OXT, int ROWS>
__global__ void conv32_v2(const float* __restrict__ in, const float* __restrict__ w,
                          const float* __restrict__ bias, float* __restrict__ out)
{
    __shared__ float sw[9 * 32 * 32];             // [kpos][ci][co] = 36 KB
    const int tid = threadIdx.x;
    const int NTH = 8 * OXT * ROWS;
    for (int i = tid * 4; i < 9 * 32 * 32; i += NTH * 4)
        *(float4*)(sw + i) = *(const float4*)(w + i);
    __syncthreads();

    const int cg  = tid & 7;
    const int oxg = (tid >> 3) % OXT;
    const int ry  = (tid >> 3) / OXT;
    const int co0 = cg * 4;
    const int ox0 = oxg * TOX;
    const int oy  = blockIdx.x * ROWS + ry;
    const int n0  = blockIdx.y * 4;
    if (oy >= OH) return;

    const float4 bv = *(const float4*)(bias + co0);

#pragma unroll 1
    for (int img = 0; img < 4; img++) {
        const int n = n0 + img;
        float acc[TOX][4];
#pragma unroll
        for (int i = 0; i < TOX; i++) {
            acc[i][0] = bv.x; acc[i][1] = bv.y; acc[i][2] = bv.z; acc[i][3] = bv.w;
        }

#pragma unroll 1
        for (int ky = 0; ky < 3; ky++) {
            const int iy = oy * 2 + ky - PAD;
            if (iy < 0 || iy >= IH) continue;
            const float* inr = in + ((size_t)(n * IH + iy) * IW) * 32;
#pragma unroll 1
            for (int kx = 0; kx < 3; kx++) {
                const float* swk = sw + ((ky * 3 + kx) * 32) * 32 + co0;
#pragma unroll
                for (int c4 = 0; c4 < 32; c4 += 4) {
                    const float4 w0 = *(const float4*)(swk + (c4 + 0) * 32);
                    const float4 w1 = *(const float4*)(swk + (c4 + 1) * 32);
                    const float4 w2 = *(const float4*)(swk + (c4 + 2) * 32);
                    const float4 w3 = *(const float4*)(swk + (c4 + 3) * 32);
#pragma unroll
                    for (int i = 0; i < TOX; i++) {
                        const int ix = (ox0 + i) * 2 + kx - PAD;
                        if (ix >= 0 && ix < IW) {
                            const float4 x = *(const float4*)(inr + (size_t)ix * 32 + c4);
                            acc[i][0] += x.x * w0.x + x.y * w1.x + x.z * w2.x + x.w * w3.x;
                            acc[i][1] += x.x * w0.y + x.y * w1.y + x.z * w2.y + x.w * w3.y;
                            acc[i][2] += x.x * w0.z + x.y * w1.z + x.z * w2.z + x.w * w3.z;
                            acc[i][3] += x.x * w0.w + x.y * w1.w + x.z * w2.w + x.w * w3.w;
                        }
                    }
                }
            }
        }
        float* outr = out + ((size_t)(n * OH + oy) * OW) * 32 + co0;
#pragma unroll
        for (int i = 0; i < TOX; i++) {
            const int ox = ox0 + i;
            if (ox < OW) {
                float4 v;
                v.x = elu_(acc[i][0]); v.y = elu_(acc[i][1]);
                v.z = elu_(acc[i][2]); v.w = elu_(acc[i][3]);
                *(float4*)(outr + (size_t)ox * 32) = v;
            }
        }
    }
}

// ---------------------------------------------------------------------------
// SGEMM: xg[2048,1024] = c4[2048,1152] @ lstm_w[0:1152, 0:1024] + lstm_b
// classic 128x128x8 tiling, 256 threads, 8x8 register micro-tile
// ---------------------------------------------------------------------------
__global__ void __launch_bounds__(256)
sgemm_xg_k(const float* __restrict__ A, const float* __restrict__ B,
           const float* __restrict__ bias, float* __restrict__ C)
{
    __shared__ float As[8][128];
    __shared__ float Bs[8][128];
    const int bx  = blockIdx.x;   // 0..7   (N tiles)
    const int by  = blockIdx.y;   // 0..15  (M tiles)
    const int tid = threadIdx.x;
    const int tr  = (tid / 16) * 8;
    const int tc  = (tid % 16) * 8;

    float acc[8][8];
#pragma unroll
    for (int i = 0; i < 8; i++)
#pragma unroll
        for (int j = 0; j < 8; j++) acc[i][j] = 0.f;

    const int ar = tid >> 1,  ac = (tid & 1) * 4;
    const int br = tid >> 5,  bc = (tid & 31) * 4;
    const float* Aptr = A + (size_t)(by * 128 + ar) * FEAT + ac;
    const float* Bptr = B + (size_t)br * 1024 + bx * 128 + bc;

    for (int k0 = 0; k0 < FEAT; k0 += 8) {
        const float4 av = *(const float4*)(Aptr + k0);
        As[ac + 0][ar] = av.x; As[ac + 1][ar] = av.y;
        As[ac + 2][ar] = av.z; As[ac + 3][ar] = av.w;
        *(float4*)&Bs[br][bc] = *(const float4*)(Bptr + (size_t)k0 * 1024);
        __syncthreads();
#pragma unroll
        for (int kk = 0; kk < 8; kk++) {
            float a[8], b[8];
#pragma unroll
            for (int i = 0; i < 8; i++) a[i] = As[kk][tr + i];
#pragma unroll
            for (int j = 0; j < 8; j++) b[j] = Bs[kk][tc + j];
#pragma unroll
            for (int i = 0; i < 8; i++)
#pragma unroll
                for (int j = 0; j < 8; j++) acc[i][j] += a[i] * b[j];
        }
        __syncthreads();
    }

#pragma unroll
    for (int i = 0; i < 8; i++) {
        const int row = by * 128 + tr + i;
        float* crow = C + (size_t)row * 1024 + bx * 128 + tc;
#pragma unroll
        for (int j = 0; j < 8; j += 4) {
            float4 v;
            v.x = acc[i][j + 0] + bias[bx * 128 + tc + j + 0];
            v.y = acc[i][j + 1] + bias[bx * 128 + tc + j + 1];
            v.z = acc[i][j + 2] + bias[bx * 128 + tc + j + 2];
            v.w = acc[i][j + 3] + bias[bx * 128 + tc + j + 3];
            *(float4*)(crow + j) = v;
        }
    }
}

// ---------------------------------------------------------------------------
// Fused LSTM recurrence + FC. One persistent block per trajectory (32 blocks),
// 256 threads = hidden size. Thread t owns c[t] and computes (i,j,f,o)[t]
// (Wh pre-interleaved as float4 per (k,t)). Dual accumulators per gate to
// halve the FFMA dependency chain. h lives in SMEM; the 18-col FC head runs
// in warps 0..5 each step, straight to d_out.
// ---------------------------------------------------------------------------
__device__ __forceinline__ float sigmoidf_(float x) { return 1.f / (1.f + expf(-x)); }

__global__ void __launch_bounds__(256)
lstm_fused_k(const float* __restrict__ xg, const float* __restrict__ whr,
             const float* __restrict__ fcw, const float* __restrict__ fcb,
             const float* __restrict__ c0, const float* __restrict__ h0,
             float* __restrict__ out)
{
    const int n   = blockIdx.x;    // trajectory
    const int tid = threadIdx.x;   // hidden index
    __shared__ float sh[HID];

    float c = c0[(size_t)n * HID + tid];
    sh[tid] = h0[(size_t)n * HID + tid];
    __syncthreads();

    const int wrp = tid >> 5, lane = tid & 31;

    for (int t = 0; t < TL; t++) {
        const float* xrow = xg + (size_t)(n * TL + t) * 1024;
        float gi0 = xrow[tid],       gi1 = 0.f;
        float gj0 = xrow[256 + tid], gj1 = 0.f;
        float gf0 = xrow[512 + tid], gf1 = 0.f;
        float go0 = xrow[768 + tid], go1 = 0.f;

#pragma unroll 2
        for (int k = 0; k < HID; k += 2) {
            const float  h0v = sh[k];
            const float4 w0  = *(const float4*)(whr + ((size_t)k * HID + tid) * 4);
            gi0 += h0v * w0.x; gj0 += h0v * w0.y; gf0 += h0v * w0.z; go0 += h0v * w0.w;
            const float  h1v = sh[k + 1];
            const float4 w1  = *(const float4*)(whr + ((size_t)(k + 1) * HID + tid) * 4);
            gi1 += h1v * w1.x; gj1 += h1v * w1.y; gf1 += h1v * w1.z; go1 += h1v * w1.w;
        }
        const float gi = gi0 + gi1, gj = gj0 + gj1, gf = gf0 + gf1, go = go0 + go1;

        const float nc = c * sigmoidf_(gf + 1.f) + sigmoidf_(gi) * tanhf(gj);
        const float nh = tanhf(nc) * sigmoidf_(go);
        c = nc;

        __syncthreads();
        sh[tid] = nh;
        __syncthreads();

        // FC head: 18 columns, warps 0..5 take 3 columns each
        if (wrp < 6) {
#pragma unroll
            for (int cc = 0; cc < 3; cc++) {
                const int col = wrp * 3 + cc;
                float s = 0.f;
#pragma unroll
                for (int k = lane; k < HID; k += 32) s += sh[k] * fcw[(size_t)k * NOUT + col];
#pragma unroll
                for (int off = 16; off; off >>= 1) s += __shfl_down_sync(0xffffffffu, s, off);
                if (lane == 0)
                    out[(size_t)(n * TL + t) * NOUT + col] = s + fcb[col];
            }
        }
    }
}

// ---------------------------------------------------------------------------
// Launch
// ---------------------------------------------------------------------------
extern "C" void kernel_launch(void* const* d_in, const int* in_sizes, int n_in,
                              void* d_out, int out_size)
{
    (void)in_sizes; (void)n_in; (void)out_size;
    const float* inp = (const float*)d_in[0];
    const float* w1  = (const float*)d_in[1];
    const float* b1  = (const float*)d_in[2];
    const float* w2  = (const float*)d_in[3];
    const float* b2  = (const float*)d_in[4];
    const float* w3  = (const float*)d_in[5];
    const float* b3  = (const float*)d_in[6];
    const float* w4  = (const float*)d_in[7];
    const float* b4  = (const float*)d_in[8];
    const float* lw  = (const float*)d_in[9];
    const float* lb  = (const float*)d_in[10];
    const float* fw  = (const float*)d_in[11];
    const float* fb  = (const float*)d_in[12];
    const float* c0  = (const float*)d_in[13];
    const float* h0  = (const float*)d_in[14];
    float* out = (float*)d_out;

    float *c1, *c2, *c3, *c4, *xg, *whr;
    cudaGetSymbolAddress((void**)&c1,  g_c1);
    cudaGetSymbolAddress((void**)&c2,  g_c2);
    cudaGetSymbolAddress((void**)&c3,  g_c3);
    cudaGetSymbolAddress((void**)&c4,  g_c4);
    cudaGetSymbolAddress((void**)&xg,  g_xg);
    cudaGetSymbolAddress((void**)&whr, g_whr);

    // Wh reorder (independent of conv chain)
    reorder_wh_k<<<256, 256>>>(lw, whr);

    // conv stack (v2: 4co x TOX register tiles, 16 FMA per input float4 load)
    // conv1: 84->42, TOX=7 OXT=6 ROWS=4 -> 192 thr, gridx=ceil(42/4)=11
    conv1_v2<7, 6, 4><<<dim3(11, NIMG / 4), 192>>>(inp, w1, b1, c1);
    // conv2: 42->21, TOX=7 OXT=3 ROWS=8 -> 192 thr, gridx=ceil(21/8)=3
    conv32_v2<42, 42, 21, 21, 0, 7, 3, 8><<<dim3(3, NIMG / 4), 192>>>(c1, w2, b2, c2);
    // conv3: 21->11, TOX=6 OXT=2 ROWS=6 -> 96 thr, gridx=2
    conv32_v2<21, 21, 11, 11, 1, 6, 2, 6><<<dim3(2, NIMG / 4), 96>>>(c2, w3, b3, c3);
    // conv4: 11->6,  TOX=3 OXT=2 ROWS=6 -> 96 thr, gridx=1
    conv32_v2<11, 11,  6,  6, 1, 3, 2, 6><<<dim3(1, NIMG / 4), 96>>>(c3, w4, b4, c4);

    // time-parallel part of the LSTM input GEMM (+ bias)
    sgemm_xg_k<<<dim3(8, 16), 256>>>(c4, lw, lb, xg);

    // recurrence + FC head fused, one persistent block per trajectory
    lstm_fused_k<<<NT, HID>>>(xg, whr, fw, fb, c0, h0, out);
}

// round 6
// speedup vs baseline: 1.5488x; 1.4582x over previous
#include <cuda_runtime.h>
#include <math.h>
#include <stdint.h>
#include <string.h>

// ---------------------------------------------------------------------------
// Problem constants
//   inputs [2048, 84, 84, 4] NHWC fp32
//   conv 3x3 s2 SAME x4 (ELU), channels 4->32->32->32->32
//   84 -> 42 -> 21 -> 11 -> 6   (FEAT = 6*6*32 = 1152)
//   LSTM size 256 over TL=64 steps, NT=32 trajectories, forget_bias=1
//   FC 256 -> 18
// ---------------------------------------------------------------------------

#define NIMG   2048
#define NT     32
#define TL     64
#define FEAT   1152
#define HID    256
#define NOUT   18

typedef unsigned long long u64;

// ---------------- packed f32x2 helpers (FFMA2: PTX-only pattern) -----------
__device__ __forceinline__ u64 bcast2(float x) {
    u64 d; asm("mov.b64 %0, {%1, %1};" : "=l"(d) : "f"(x)); return d;
}
__device__ __forceinline__ u64 pack2(float a, float b) {
    u64 d; asm("mov.b64 %0, {%1, %2};" : "=l"(d) : "f"(a), "f"(b)); return d;
}
__device__ __forceinline__ float2 unpack2(u64 v) {
    float2 r; asm("mov.b64 {%0, %1}, %2;" : "=f"(r.x), "=f"(r.y) : "l"(v)); return r;
}
__device__ __forceinline__ void fma2(u64& d, u64 a, u64 b) {
    asm("fma.rn.f32x2 %0, %1, %2, %0;" : "+l"(d) : "l"(a), "l"(b));
}

__device__ __forceinline__ float elu_(float v) { return v > 0.f ? v : (__expf(v) - 1.f); }

// ------------------------- device scratch (no cudaMalloc allowed) ----------
__device__ float g_c1[(size_t)NIMG * 42 * 42 * 32];   // 462 MB
__device__ float g_c2[(size_t)NIMG * 21 * 21 * 32];   // 116 MB
__device__ float g_c3[(size_t)NIMG * 11 * 11 * 32];   //  32 MB
__device__ float g_c4[(size_t)NIMG * 6 * 6 * 32];     //   9 MB
__device__ float g_xg[(size_t)NIMG * 1024];           //   8 MB  x@Wx + b
__device__ float g_whr[HID * HID * 4];                //   1 MB  Wh interleaved

// ---------------------------------------------------------------------------
// Wh reorder: whr[(k*256 + t)*4 + g] = lstm_w[(1152+k)*1024 + g*256 + t]
// ---------------------------------------------------------------------------
__global__ void reorder_wh_k(const float* __restrict__ lw, float* __restrict__ whr)
{
    const int k = blockIdx.x;     // 0..255  (h input dim)
    const int t = threadIdx.x;    // 0..255  (hidden index)
    const float* row = lw + (size_t)(FEAT + k) * 1024;
    float4 v;
    v.x = row[t];          // i
    v.y = row[256 + t];    // j
    v.z = row[512 + t];    // f
    v.w = row[768 + t];    // o
    *(float4*)(whr + ((size_t)k * 256 + t) * 4) = v;
}

// ---------------------------------------------------------------------------
// conv1 v3: Cin=4 -> Cout=32, 84x84 -> 42x42, pad_begin=0 (SAME pads at end).
// One image per block, 288 threads = 8 co-groups x 6 ox-tiles(TOX=7) x 6 rows.
// f32x2 accumulators over co pairs: 1 input float4 -> 4 bcast + 8 fma2.
// ---------------------------------------------------------------------------
__global__ void __launch_bounds__(288)
conv1_v3(const float* __restrict__ in, const float* __restrict__ w,
         const float* __restrict__ bias, float* __restrict__ out)
{
    __shared__ __align__(16) float sw[9 * 4 * 32];    // [kpos][ci][co]
    const int tid = threadIdx.x;
    if (tid < 288) *(float4*)(sw + tid * 4) = *(const float4*)(w + tid * 4);
    __syncthreads();

    const int cg   = tid & 7;
    const int rest = tid >> 3;
    const int oxg  = rest % 6;
    const int ry   = rest / 6;
    const int oy   = blockIdx.x * 6 + ry;             // 0..41 (7*6 exact)
    const int n    = blockIdx.y;
    const int co0  = cg * 4;
    const int ox0  = oxg * 7;                          // 6*7 = 42 exact

    u64 aL[7], aH[7];
    const u64 bL = pack2(bias[co0],     bias[co0 + 1]);
    const u64 bH = pack2(bias[co0 + 2], bias[co0 + 3]);
#pragma unroll
    for (int i = 0; i < 7; i++) { aL[i] = bL; aH[i] = bH; }

#pragma unroll
    for (int ky = 0; ky < 3; ky++) {
        const int iy = oy * 2 + ky;
        if (iy >= 84) continue;
        const float* inr = in + ((size_t)(n * 84 + iy) * 84) * 4;
#pragma unroll
        for (int kx = 0; kx < 3; kx++) {
            const float* swk = sw + ((ky * 3 + kx) * 4) * 32 + co0;
            const ulonglong2 w0 = *(const ulonglong2*)(swk);
            const ulonglong2 w1 = *(const ulonglong2*)(swk + 32);
            const ulonglong2 w2 = *(const ulonglong2*)(swk + 64);
            const ulonglong2 w3 = *(const ulonglong2*)(swk + 96);
#pragma unroll
            for (int i = 0; i < 7; i++) {
                const int ix = (ox0 + i) * 2 + kx;
                if (ix < 84) {
                    const float4 x = *(const float4*)(inr + (size_t)ix * 4);
                    u64 xb;
                    xb = bcast2(x.x); fma2(aL[i], xb, w0.x); fma2(aH[i], xb, w0.y);
                    xb = bcast2(x.y); fma2(aL[i], xb, w1.x); fma2(aH[i], xb, w1.y);
                    xb = bcast2(x.z); fma2(aL[i], xb, w2.x); fma2(aH[i], xb, w2.y);
                    xb = bcast2(x.w); fma2(aL[i], xb, w3.x); fma2(aH[i], xb, w3.y);
                }
            }
        }
    }
    float* outr = out + ((size_t)(n * 42 + oy) * 42) * 32 + co0;
#pragma unroll
    for (int i = 0; i < 7; i++) {
        const float2 lo = unpack2(aL[i]), hi = unpack2(aH[i]);
        float4 v;
        v.x = elu_(lo.x); v.y = elu_(lo.y); v.z = elu_(hi.x); v.w = elu_(hi.y);
        *(float4*)(outr + (size_t)(ox0 + i) * 32) = v;
    }
}

// ---------------------------------------------------------------------------
// convN v3: Cin=32 -> Cout=32, f32x2 over co pairs.
// block = 8 co-groups * OXT * ROWS * IPB threads; IPB images per block
// (parallel, not serial). grid (ceil(OH/ROWS), NIMG/IPB).
// Per (kpos, ci-quad): 4 LDS.128 weights + TOX LDG.128 inputs ->
//   TOX * (4 mov.b64 + 8 fma2) = 16*TOX MACs at half fma-pipe cost.
// ---------------------------------------------------------------------------
template <int IH, int IW, int OH, int OW, int PAD, int TOX, int OXT, int ROWS, int IPB>
__global__ void conv32_v3(const float* __restrict__ in, const float* __restrict__ w,
                          const float* __restrict__ bias, float* __restrict__ out)
{
    __shared__ __align__(16) float sw[9 * 32 * 32];   // [kpos][ci][co] = 36 KB
    const int tid = threadIdx.x;
    const int NTH = 8 * OXT * ROWS * IPB;
    for (int i = tid * 4; i < 9 * 32 * 32; i += NTH * 4)
        *(float4*)(sw + i) = *(const float4*)(w + i);
    __syncthreads();

    const int cg  = tid & 7;
    int rest      = tid >> 3;
    const int oxg = rest % OXT;  rest /= OXT;
    const int ry  = rest % ROWS;
    const int img = rest / ROWS;
    const int co0 = cg * 4;
    const int ox0 = oxg * TOX;
    const int oy  = blockIdx.x * ROWS + ry;
    const int n   = blockIdx.y * IPB + img;
    if (oy >= OH) return;

    u64 aL[TOX], aH[TOX];
    const u64 bL = pack2(bias[co0],     bias[co0 + 1]);
    const u64 bH = pack2(bias[co0 + 2], bias[co0 + 3]);
#pragma unroll
    for (int i = 0; i < TOX; i++) { aL[i] = bL; aH[i] = bH; }

#pragma unroll
    for (int ky = 0; ky < 3; ky++) {
        const int iy = oy * 2 + ky - PAD;
        if (iy < 0 || iy >= IH) continue;
        const float* inr = in + ((size_t)(n * IH + iy) * IW) * 32;
#pragma unroll
        for (int kx = 0; kx < 3; kx++) {
            const float* pin[TOX];
            bool ok[TOX];
#pragma unroll
            for (int i = 0; i < TOX; i++) {
                const int ix = (ox0 + i) * 2 + kx - PAD;
                ok[i]  = (ix >= 0) && (ix < IW);
                pin[i] = inr + (size_t)ix * 32;
            }
            const float* swk = sw + ((ky * 3 + kx) * 32) * 32 + co0;
#pragma unroll
            for (int c4 = 0; c4 < 32; c4 += 4) {
                const ulonglong2 w0 = *(const ulonglong2*)(swk + (c4 + 0) * 32);
                const ulonglong2 w1 = *(const ulonglong2*)(swk + (c4 + 1) * 32);
                const ulonglong2 w2 = *(const ulonglong2*)(swk + (c4 + 2) * 32);
                const ulonglong2 w3 = *(const ulonglong2*)(swk + (c4 + 3) * 32);
#pragma unroll
                for (int i = 0; i < TOX; i++) {
                    if (ok[i]) {
                        const float4 x = *(const float4*)(pin[i] + c4);
                        u64 xb;
                        xb = bcast2(x.x); fma2(aL[i], xb, w0.x); fma2(aH[i], xb, w0.y);
                        xb = bcast2(x.y); fma2(aL[i], xb, w1.x); fma2(aH[i], xb, w1.y);
                        xb = bcast2(x.z); fma2(aL[i], xb, w2.x); fma2(aH[i], xb, w2.y);
                        xb = bcast2(x.w); fma2(aL[i], xb, w3.x); fma2(aH[i], xb, w3.y);
                    }
                }
            }
        }
    }
    float* outr = out + ((size_t)(n * OH + oy) * OW) * 32 + co0;
#pragma unroll
    for (int i = 0; i < TOX; i++) {
        if (ox0 + i < OW) {
            const float2 lo = unpack2(aL[i]), hi = unpack2(aH[i]);
            float4 v;
            v.x = elu_(lo.x); v.y = elu_(lo.y); v.z = elu_(hi.x); v.w = elu_(hi.y);
            *(float4*)(outr + (size_t)(ox0 + i) * 32) = v;
        }
    }
}

// ---------------------------------------------------------------------------
// SGEMM: xg[2048,1024] = c4[2048,1152] @ lstm_w[0:1152, 0:1024] + lstm_b
// 128x128x8 tiling, 256 threads, 8x8 micro-tile as f32x2 pairs over columns:
// per k-step: 4 LDS.128 + 8 mov.b64 + 32 fma2 (vs 64 FFMA).
// ---------------------------------------------------------------------------
__global__ void __launch_bounds__(256)
sgemm_xg_v2(const float* __restrict__ A, const float* __restrict__ B,
            const float* __restrict__ bias, float* __restrict__ C)
{
    __shared__ __align__(16) float As[8][128];
    __shared__ __align__(16) float Bs[8][128];
    const int bx  = blockIdx.x;   // 0..7   (N tiles)
    const int by  = blockIdx.y;   // 0..15  (M tiles)
    const int tid = threadIdx.x;
    const int tr  = (tid / 16) * 8;
    const int tc  = (tid % 16) * 8;

    u64 acc[8][4];
#pragma unroll
    for (int i = 0; i < 8; i++)
#pragma unroll
        for (int j = 0; j < 4; j++) acc[i][j] = 0ull;

    const int ar = tid >> 1,  ac = (tid & 1) * 4;
    const int br = tid >> 5,  bc = (tid & 31) * 4;
    const float* Aptr = A + (size_t)(by * 128 + ar) * FEAT + ac;
    const float* Bptr = B + (size_t)br * 1024 + bx * 128 + bc;

    for (int k0 = 0; k0 < FEAT; k0 += 8) {
        const float4 av = *(const float4*)(Aptr + k0);
        As[ac + 0][ar] = av.x; As[ac + 1][ar] = av.y;
        As[ac + 2][ar] = av.z; As[ac + 3][ar] = av.w;
        *(float4*)&Bs[br][bc] = *(const float4*)(Bptr + (size_t)k0 * 1024);
        __syncthreads();
#pragma unroll
        for (int kk = 0; kk < 8; kk++) {
            const float4 a0 = *(const float4*)&As[kk][tr];
            const float4 a1 = *(const float4*)&As[kk][tr + 4];
            const ulonglong2 b0 = *(const ulonglong2*)&Bs[kk][tc];
            const ulonglong2 b1 = *(const ulonglong2*)&Bs[kk][tc + 4];
            const float a[8] = {a0.x, a0.y, a0.z, a0.w, a1.x, a1.y, a1.z, a1.w};
#pragma unroll
            for (int i = 0; i < 8; i++) {
                const u64 ab = bcast2(a[i]);
                fma2(acc[i][0], ab, b0.x);
                fma2(acc[i][1], ab, b0.y);
                fma2(acc[i][2], ab, b1.x);
                fma2(acc[i][3], ab, b1.y);
            }
        }
        __syncthreads();
    }

#pragma unroll
    for (int i = 0; i < 8; i++) {
        const int row = by * 128 + tr + i;
        float* crow = C + (size_t)row * 1024 + bx * 128 + tc;
#pragma unroll
        for (int j = 0; j < 2; j++) {
            const float2 p0 = unpack2(acc[i][j * 2 + 0]);
            const float2 p1 = unpack2(acc[i][j * 2 + 1]);
            float4 v;
            v.x = p0.x + bias[bx * 128 + tc + j * 4 + 0];
            v.y = p0.y + bias[bx * 128 + tc + j * 4 + 1];
            v.z = p1.x + bias[bx * 128 + tc + j * 4 + 2];
            v.w = p1.y + bias[bx * 128 + tc + j * 4 + 3];
            *(float4*)(crow + j * 4) = v;
        }
    }
}

// ---------------------------------------------------------------------------
// Fused LSTM recurrence + FC. One persistent block per trajectory (32 blocks),
// 256 threads = hidden size. Thread t owns c[t] and accumulates gate pairs
// (i,j) and (f,o) as f32x2 with dual chains. h lives in SMEM; 18-col FC head
// runs in warps 0..5 each step, straight to d_out.
// ---------------------------------------------------------------------------
__device__ __forceinline__ float sigmoidf_(float x) { return 1.f / (1.f + expf(-x)); }

__global__ void __launch_bounds__(256)
lstm_fused_v2(const float* __restrict__ xg, const float* __restrict__ whr,
              const float* __restrict__ fcw, const float* __restrict__ fcb,
              const float* __restrict__ c0, const float* __restrict__ h0,
              float* __restrict__ out)
{
    const int n   = blockIdx.x;    // trajectory
    const int tid = threadIdx.x;   // hidden index
    __shared__ float sh[HID];

    float c = c0[(size_t)n * HID + tid];
    sh[tid] = h0[(size_t)n * HID + tid];
    __syncthreads();

    const int wrp = tid >> 5, lane = tid & 31;

    for (int t = 0; t < TL; t++) {
        const float* xrow = xg + (size_t)(n * TL + t) * 1024;
        u64 gij0 = pack2(xrow[tid],       xrow[256 + tid]), gij1 = 0ull;
        u64 gfo0 = pack2(xrow[512 + tid], xrow[768 + tid]), gfo1 = 0ull;

#pragma unroll 4
        for (int k = 0; k < HID; k += 2) {
            const u64 hb0 = bcast2(sh[k]);
            const ulonglong2 w0 = *(const ulonglong2*)(whr + ((size_t)k * HID + tid) * 4);
            fma2(gij0, hb0, w0.x); fma2(gfo0, hb0, w0.y);
            const u64 hb1 = bcast2(sh[k + 1]);
            const ulonglong2 w1 = *(const ulonglong2*)(whr + ((size_t)(k + 1) * HID + tid) * 4);
            fma2(gij1, hb1, w1.x); fma2(gfo1, hb1, w1.y);
        }
        const float2 ij0 = unpack2(gij0), ij1 = unpack2(gij1);
        const float2 fo0 = unpack2(gfo0), fo1 = unpack2(gfo1);
        const float gi = ij0.x + ij1.x, gj = ij0.y + ij1.y;
        const float gf = fo0.x + fo1.x, go = fo0.y + fo1.y;

        const float nc = c * sigmoidf_(gf + 1.f) + sigmoidf_(gi) * tanhf(gj);
        const float nh = tanhf(nc) * sigmoidf_(go);
        c = nc;

        __syncthreads();
        sh[tid] = nh;
        __syncthreads();

        // FC head: 18 columns, warps 0..5 take 3 columns each
        if (wrp < 6) {
#pragma unroll
            for (int cc = 0; cc < 3; cc++) {
                const int col = wrp * 3 + cc;
                float s = 0.f;
#pragma unroll
                for (int k = lane; k < HID; k += 32) s += sh[k] * fcw[(size_t)k * NOUT + col];
#pragma unroll
                for (int off = 16; off; off >>= 1) s += __shfl_down_sync(0xffffffffu, s, off);
                if (lane == 0)
                    out[(size_t)(n * TL + t) * NOUT + col] = s + fcb[col];
            }
        }
    }
}

// ---------------------------------------------------------------------------
// Launch
// ---------------------------------------------------------------------------
extern "C" void kernel_launch(void* const* d_in, const int* in_sizes, int n_in,
                              void* d_out, int out_size)
{
    (void)in_sizes; (void)n_in; (void)out_size;
    const float* inp = (const float*)d_in[0];
    const float* w1  = (const float*)d_in[1];
    const float* b1  = (const float*)d_in[2];
    const float* w2  = (const float*)d_in[3];
    const float* b2  = (const float*)d_in[4];
    const float* w3  = (const float*)d_in[5];
    const float* b3  = (const float*)d_in[6];
    const float* w4  = (const float*)d_in[7];
    const float* b4  = (const float*)d_in[8];
    const float* lw  = (const float*)d_in[9];
    const float* lb  = (const float*)d_in[10];
    const float* fw  = (const float*)d_in[11];
    const float* fb  = (const float*)d_in[12];
    const float* c0  = (const float*)d_in[13];
    const float* h0  = (const float*)d_in[14];
    float* out = (float*)d_out;

    float *c1, *c2, *c3, *c4, *xg, *whr;
    cudaGetSymbolAddress((void**)&c1,  g_c1);
    cudaGetSymbolAddress((void**)&c2,  g_c2);
    cudaGetSymbolAddress((void**)&c3,  g_c3);
    cudaGetSymbolAddress((void**)&c4,  g_c4);
    cudaGetSymbolAddress((void**)&xg,  g_xg);
    cudaGetSymbolAddress((void**)&whr, g_whr);

    // Wh reorder (independent of conv chain)
    reorder_wh_k<<<256, 256>>>(lw, whr);

    // conv stack — one image per block (4 for conv4), f32x2 inner loops
    // conv1: 84->42, 288 thr (8cg x 6oxt(TOX7) x 6rows), grid (7, 2048)
    conv1_v3<<<dim3(7, NIMG), 288>>>(inp, w1, b1, c1);
    // conv2: 42->21, TOX=7 OXT=3 ROWS=8 IPB=1 -> 192 thr, grid (3, 2048)
    conv32_v3<42, 42, 21, 21, 0, 7, 3, 8, 1><<<dim3(3, NIMG), 192>>>(c1, w2, b2, c2);
    // conv3: 21->11, TOX=6 OXT=2 ROWS=12 IPB=1 -> 192 thr, grid (1, 2048)
    conv32_v3<21, 21, 11, 11, 1, 6, 2, 12, 1><<<dim3(1, NIMG), 192>>>(c2, w3, b3, c3);
    // conv4: 11->6,  TOX=6 OXT=1 ROWS=6 IPB=4 -> 192 thr, grid (1, 512)
    conv32_v3<11, 11,  6,  6, 1, 6, 1, 6, 4><<<dim3(1, NIMG / 4), 192>>>(c3, w4, b4, c4);

    // time-parallel part of the LSTM input GEMM (+ bias), f32x2 micro-kernel
    sgemm_xg_v2<<<dim3(8, 16), 256>>>(c4, lw, lb, xg);

    // recurrence + FC head fused, one persistent block per trajectory
    lstm_fused_v2<<<NT, HID>>>(xg, whr, fw, fb, c0, h0, out);
}

// round 7
// speedup vs baseline: 1.5753x; 1.0171x over previous
#include <cuda_runtime.h>
#include <math.h>
#include <stdint.h>
#include <string.h>

// ---------------------------------------------------------------------------
// Problem constants
//   inputs [2048, 84, 84, 4] NHWC fp32
//   conv 3x3 s2 SAME x4 (ELU), channels 4->32->32->32->32
//   84 -> 42 -> 21 -> 11 -> 6   (FEAT = 6*6*32 = 1152)
//   LSTM size 256 over TL=64 steps, NT=32 trajectories, forget_bias=1
//   FC 256 -> 18
// ---------------------------------------------------------------------------

#define NIMG   2048
#define NT     32
#define TL     64
#define FEAT   1152
#define HID    256
#define NOUT   18

typedef unsigned long long u64;

// ---------------- packed f32x2 helpers (FFMA2: PTX-only pattern) -----------
__device__ __forceinline__ u64 bcast2(float x) {
    u64 d; asm("mov.b64 %0, {%1, %1};" : "=l"(d) : "f"(x)); return d;
}
__device__ __forceinline__ u64 pack2(float a, float b) {
    u64 d; asm("mov.b64 %0, {%1, %2};" : "=l"(d) : "f"(a), "f"(b)); return d;
}
__device__ __forceinline__ float2 unpack2(u64 v) {
    float2 r; asm("mov.b64 {%0, %1}, %2;" : "=f"(r.x), "=f"(r.y) : "l"(v)); return r;
}
__device__ __forceinline__ void fma2(u64& d, u64 a, u64 b) {
    asm("fma.rn.f32x2 %0, %1, %2, %0;" : "+l"(d) : "l"(a), "l"(b));
}

__device__ __forceinline__ float elu_(float v) { return v > 0.f ? v : (__expf(v) - 1.f); }

// ------------------------- device scratch (no cudaMalloc allowed) ----------
__device__ float g_c1[(size_t)NIMG * 42 * 42 * 32];   // 462 MB
__device__ float g_c2[(size_t)NIMG * 21 * 21 * 32];   // 116 MB
__device__ float g_c3[(size_t)NIMG * 11 * 11 * 32];   //  32 MB
__device__ float g_c4[(size_t)NIMG * 6 * 6 * 32];     //   9 MB
__device__ float g_xg[(size_t)NIMG * 1024];           //   8 MB  x@Wx + b
__device__ float g_whr[HID * HID * 4];                //   1 MB  Wh interleaved

// ---------------------------------------------------------------------------
// Wh reorder: whr[(k*256 + t)*4 + g] = lstm_w[(1152+k)*1024 + g*256 + t]
// ---------------------------------------------------------------------------
__global__ void reorder_wh_k(const float* __restrict__ lw, float* __restrict__ whr)
{
    const int k = blockIdx.x;     // 0..255  (h input dim)
    const int t = threadIdx.x;    // 0..255  (hidden index)
    const float* row = lw + (size_t)(FEAT + k) * 1024;
    float4 v;
    v.x = row[t];          // i
    v.y = row[256 + t];    // j
    v.z = row[512 + t];    // f
    v.w = row[768 + t];    // o
    *(float4*)(whr + ((size_t)k * 256 + t) * 4) = v;
}

// ---------------------------------------------------------------------------
// conv1: Cin=4 -> Cout=32, 84x84 -> 42x42, pad_begin=0 (SAME pads at end).
// One image per block, 288 threads = 8 co-groups x 6 ox-tiles(TOX=7) x 6 rows.
// f32x2 accumulators over co pairs. launch_bounds caps regs for 2 blocks/SM.
// ---------------------------------------------------------------------------
__global__ void __launch_bounds__(288, 2)
conv1_v3(const float* __restrict__ in, const float* __restrict__ w,
         const float* __restrict__ bias, float* __restrict__ out)
{
    __shared__ __align__(16) float sw[9 * 4 * 32];    // [kpos][ci][co]
    const int tid = threadIdx.x;
    if (tid < 288) *(float4*)(sw + tid * 4) = *(const float4*)(w + tid * 4);
    __syncthreads();

    const int cg   = tid & 7;
    const int rest = tid >> 3;
    const int oxg  = rest % 6;
    const int ry   = rest / 6;
    const int oy   = blockIdx.x * 6 + ry;             // 0..41 (7*6 exact)
    const int n    = blockIdx.y;
    const int co0  = cg * 4;
    const int ox0  = oxg * 7;                          // 6*7 = 42 exact

    u64 aL[7], aH[7];
    const u64 bL = pack2(bias[co0],     bias[co0 + 1]);
    const u64 bH = pack2(bias[co0 + 2], bias[co0 + 3]);
#pragma unroll
    for (int i = 0; i < 7; i++) { aL[i] = bL; aH[i] = bH; }

#pragma unroll 1
    for (int ky = 0; ky < 3; ky++) {
        const int iy = oy * 2 + ky;
        if (iy >= 84) continue;
        const float* inr = in + ((size_t)(n * 84 + iy) * 84) * 4;
#pragma unroll
        for (int kx = 0; kx < 3; kx++) {
            const float* swk = sw + ((ky * 3 + kx) * 4) * 32 + co0;
            const ulonglong2 w0 = *(const ulonglong2*)(swk);
            const ulonglong2 w1 = *(const ulonglong2*)(swk + 32);
            const ulonglong2 w2 = *(const ulonglong2*)(swk + 64);
            const ulonglong2 w3 = *(const ulonglong2*)(swk + 96);
#pragma unroll
            for (int i = 0; i < 7; i++) {
                const int ix = (ox0 + i) * 2 + kx;
                if (ix < 84) {
                    const float4 x = *(const float4*)(inr + (size_t)ix * 4);
                    u64 xb;
                    xb = bcast2(x.x); fma2(aL[i], xb, w0.x); fma2(aH[i], xb, w0.y);
                    xb = bcast2(x.y); fma2(aL[i], xb, w1.x); fma2(aH[i], xb, w1.y);
                    xb = bcast2(x.z); fma2(aL[i], xb, w2.x); fma2(aH[i], xb, w2.y);
                    xb = bcast2(x.w); fma2(aL[i], xb, w3.x); fma2(aH[i], xb, w3.y);
                }
            }
        }
    }
    float* outr = out + ((size_t)(n * 42 + oy) * 42) * 32 + co0;
#pragma unroll
    for (int i = 0; i < 7; i++) {
        const float2 lo = unpack2(aL[i]), hi = unpack2(aH[i]);
        float4 v;
        v.x = elu_(lo.x); v.y = elu_(lo.y); v.z = elu_(hi.x); v.w = elu_(hi.y);
        *(float4*)(outr + (size_t)(ox0 + i) * 32) = v;
    }
}

// ---------------------------------------------------------------------------
// convN: Cin=32 -> Cout=32, f32x2 over co pairs.
// block = 8 co-groups * OXT * ROWS * IPB threads; IPB images in parallel.
// launch_bounds(NTH, 3) caps regs ~113 -> 3 blocks (18 warps) per SM.
// ky loop kept rolled to bound live ranges; kx/c4/TOX fully unrolled.
// ---------------------------------------------------------------------------
template <int IH, int IW, int OH, int OW, int PAD, int TOX, int OXT, int ROWS, int IPB>
__global__ void __launch_bounds__(8 * OXT * ROWS * IPB, 3)
conv32_v3(const float* __restrict__ in, const float* __restrict__ w,
          const float* __restrict__ bias, float* __restrict__ out)
{
    __shared__ __align__(16) float sw[9 * 32 * 32];   // [kpos][ci][co] = 36 KB
    const int tid = threadIdx.x;
    const int NTH = 8 * OXT * ROWS * IPB;
    for (int i = tid * 4; i < 9 * 32 * 32; i += NTH * 4)
        *(float4*)(sw + i) = *(const float4*)(w + i);
    __syncthreads();

    const int cg  = tid & 7;
    int rest      = tid >> 3;
    const int oxg = rest % OXT;  rest /= OXT;
    const int ry  = rest % ROWS;
    const int img = rest / ROWS;
    const int co0 = cg * 4;
    const int ox0 = oxg * TOX;
    const int oy  = blockIdx.x * ROWS + ry;
    const int n   = blockIdx.y * IPB + img;
    if (oy >= OH) return;

    u64 aL[TOX], aH[TOX];
    const u64 bL = pack2(bias[co0],     bias[co0 + 1]);
    const u64 bH = pack2(bias[co0 + 2], bias[co0 + 3]);
#pragma unroll
    for (int i = 0; i < TOX; i++) { aL[i] = bL; aH[i] = bH; }

#pragma unroll 1
    for (int ky = 0; ky < 3; ky++) {
        const int iy = oy * 2 + ky - PAD;
        if (iy < 0 || iy >= IH) continue;
        const float* inr = in + ((size_t)(n * IH + iy) * IW) * 32;
#pragma unroll
        for (int kx = 0; kx < 3; kx++) {
            const float* swk = sw + ((ky * 3 + kx) * 32) * 32 + co0;
#pragma unroll
            for (int c4 = 0; c4 < 32; c4 += 4) {
                const ulonglong2 w0 = *(const ulonglong2*)(swk + (c4 + 0) * 32);
                const ulonglong2 w1 = *(const ulonglong2*)(swk + (c4 + 1) * 32);
                const ulonglong2 w2 = *(const ulonglong2*)(swk + (c4 + 2) * 32);
                const ulonglong2 w3 = *(const ulonglong2*)(swk + (c4 + 3) * 32);
#pragma unroll
                for (int i = 0; i < TOX; i++) {
                    const int ix = (ox0 + i) * 2 + kx - PAD;
                    if (ix >= 0 && ix < IW) {
                        const float4 x = *(const float4*)(inr + (size_t)ix * 32 + c4);
                        u64 xb;
                        xb = bcast2(x.x); fma2(aL[i], xb, w0.x); fma2(aH[i], xb, w0.y);
                        xb = bcast2(x.y); fma2(aL[i], xb, w1.x); fma2(aH[i], xb, w1.y);
                        xb = bcast2(x.z); fma2(aL[i], xb, w2.x); fma2(aH[i], xb, w2.y);
                        xb = bcast2(x.w); fma2(aL[i], xb, w3.x); fma2(aH[i], xb, w3.y);
                    }
                }
            }
        }
    }
    float* outr = out + ((size_t)(n * OH + oy) * OW) * 32 + co0;
#pragma unroll
    for (int i = 0; i < TOX; i++) {
        if (ox0 + i < OW) {
            const float2 lo = unpack2(aL[i]), hi = unpack2(aH[i]);
            float4 v;
            v.x = elu_(lo.x); v.y = elu_(lo.y); v.z = elu_(hi.x); v.w = elu_(hi.y);
            *(float4*)(outr + (size_t)(ox0 + i) * 32) = v;
        }
    }
}

// ---------------------------------------------------------------------------
// SGEMM: xg[2048,1024] = c4[2048,1152] @ lstm_w[0:1152, 0:1024] + lstm_b
// 128x128x8 tiling, 256 threads, 8x8 micro-tile as f32x2 pairs over columns.
// ---------------------------------------------------------------------------
__global__ void __launch_bounds__(256, 2)
sgemm_xg_v2(const float* __restrict__ A, const float* __restrict__ B,
            const float* __restrict__ bias, float* __restrict__ C)
{
    __shared__ __align__(16) float As[8][128];
    __shared__ __align__(16) float Bs[8][128];
    const int bx  = blockIdx.x;   // 0..7   (N tiles)
    const int by  = blockIdx.y;   // 0..15  (M tiles)
    const int tid = threadIdx.x;
    const int tr  = (tid / 16) * 8;
    const int tc  = (tid % 16) * 8;

    u64 acc[8][4];
#pragma unroll
    for (int i = 0; i < 8; i++)
#pragma unroll
        for (int j = 0; j < 4; j++) acc[i][j] = 0ull;

    const int ar = tid >> 1,  ac = (tid & 1) * 4;
    const int br = tid >> 5,  bc = (tid & 31) * 4;
    const float* Aptr = A + (size_t)(by * 128 + ar) * FEAT + ac;
    const float* Bptr = B + (size_t)br * 1024 + bx * 128 + bc;

    for (int k0 = 0; k0 < FEAT; k0 += 8) {
        const float4 av = *(const float4*)(Aptr + k0);
        As[ac + 0][ar] = av.x; As[ac + 1][ar] = av.y;
        As[ac + 2][ar] = av.z; As[ac + 3][ar] = av.w;
        *(float4*)&Bs[br][bc] = *(const float4*)(Bptr + (size_t)k0 * 1024);
        __syncthreads();
#pragma unroll
        for (int kk = 0; kk < 8; kk++) {
            const float4 a0 = *(const float4*)&As[kk][tr];
            const float4 a1 = *(const float4*)&As[kk][tr + 4];
            const ulonglong2 b0 = *(const ulonglong2*)&Bs[kk][tc];
            const ulonglong2 b1 = *(const ulonglong2*)&Bs[kk][tc + 4];
            const float a[8] = {a0.x, a0.y, a0.z, a0.w, a1.x, a1.y, a1.z, a1.w};
#pragma unroll
            for (int i = 0; i < 8; i++) {
                const u64 ab = bcast2(a[i]);
                fma2(acc[i][0], ab, b0.x);
                fma2(acc[i][1], ab, b0.y);
                fma2(acc[i][2], ab, b1.x);
                fma2(acc[i][3], ab, b1.y);
            }
        }
        __syncthreads();
    }

#pragma unroll
    for (int i = 0; i < 8; i++) {
        const int row = by * 128 + tr + i;
        float* crow = C + (size_t)row * 1024 + bx * 128 + tc;
#pragma unroll
        for (int j = 0; j < 2; j++) {
            const float2 p0 = unpack2(acc[i][j * 2 + 0]);
            const float2 p1 = unpack2(acc[i][j * 2 + 1]);
            float4 v;
            v.x = p0.x + bias[bx * 128 + tc + j * 4 + 0];
            v.y = p0.y + bias[bx * 128 + tc + j * 4 + 1];
            v.z = p1.x + bias[bx * 128 + tc + j * 4 + 2];
            v.w = p1.y + bias[bx * 128 + tc + j * 4 + 3];
            *(float4*)(crow + j * 4) = v;
        }
    }
}

// ---------------------------------------------------------------------------
// Fused LSTM recurrence + FC. One persistent block per trajectory (32 blocks),
// 256 threads = hidden size. Thread t owns c[t] and accumulates gate pairs
// (i,j) and (f,o) as f32x2 with dual chains. h lives in SMEM; 18-col FC head
// runs in warps 0..5 each step, straight to d_out.
// ---------------------------------------------------------------------------
__device__ __forceinline__ float sigmoidf_(float x) { return 1.f / (1.f + expf(-x)); }

__global__ void __launch_bounds__(256)
lstm_fused_v2(const float* __restrict__ xg, const float* __restrict__ whr,
              const float* __restrict__ fcw, const float* __restrict__ fcb,
              const float* __restrict__ c0, const float* __restrict__ h0,
              float* __restrict__ out)
{
    const int n   = blockIdx.x;    // trajectory
    const int tid = threadIdx.x;   // hidden index
    __shared__ float sh[HID];

    float c = c0[(size_t)n * HID + tid];
    sh[tid] = h0[(size_t)n * HID + tid];
    __syncthreads();

    const int wrp = tid >> 5, lane = tid & 31;

    for (int t = 0; t < TL; t++) {
        const float* xrow = xg + (size_t)(n * TL + t) * 1024;
        u64 gij0 = pack2(xrow[tid],       xrow[256 + tid]), gij1 = 0ull;
        u64 gfo0 = pack2(xrow[512 + tid], xrow[768 + tid]), gfo1 = 0ull;

#pragma unroll 4
        for (int k = 0; k < HID; k += 2) {
            const u64 hb0 = bcast2(sh[k]);
            const ulonglong2 w0 = *(const ulonglong2*)(whr + ((size_t)k * HID + tid) * 4);
            fma2(gij0, hb0, w0.x); fma2(gfo0, hb0, w0.y);
            const u64 hb1 = bcast2(sh[k + 1]);
            const ulonglong2 w1 = *(const ulonglong2*)(whr + ((size_t)(k + 1) * HID + tid) * 4);
            fma2(gij1, hb1, w1.x); fma2(gfo1, hb1, w1.y);
        }
        const float2 ij0 = unpack2(gij0), ij1 = unpack2(gij1);
        const float2 fo0 = unpack2(gfo0), fo1 = unpack2(gfo1);
        const float gi = ij0.x + ij1.x, gj = ij0.y + ij1.y;
        const float gf = fo0.x + fo1.x, go = fo0.y + fo1.y;

        const float nc = c * sigmoidf_(gf + 1.f) + sigmoidf_(gi) * tanhf(gj);
        const float nh = tanhf(nc) * sigmoidf_(go);
        c = nc;

        __syncthreads();
        sh[tid] = nh;
        __syncthreads();

        // FC head: 18 columns, warps 0..5 take 3 columns each
        if (wrp < 6) {
#pragma unroll
            for (int cc = 0; cc < 3; cc++) {
                const int col = wrp * 3 + cc;
                float s = 0.f;
#pragma unroll
                for (int k = lane; k < HID; k += 32) s += sh[k] * fcw[(size_t)k * NOUT + col];
#pragma unroll
                for (int off = 16; off; off >>= 1) s += __shfl_down_sync(0xffffffffu, s, off);
                if (lane == 0)
                    out[(size_t)(n * TL + t) * NOUT + col] = s + fcb[col];
            }
        }
    }
}

// ---------------------------------------------------------------------------
// Launch
// ---------------------------------------------------------------------------
extern "C" void kernel_launch(void* const* d_in, const int* in_sizes, int n_in,
                              void* d_out, int out_size)
{
    (void)in_sizes; (void)n_in; (void)out_size;
    const float* inp = (const float*)d_in[0];
    const float* w1  = (const float*)d_in[1];
    const float* b1  = (const float*)d_in[2];
    const float* w2  = (const float*)d_in[3];
    const float* b2  = (const float*)d_in[4];
    const float* w3  = (const float*)d_in[5];
    const float* b3  = (const float*)d_in[6];
    const float* w4  = (const float*)d_in[7];
    const float* b4  = (const float*)d_in[8];
    const float* lw  = (const float*)d_in[9];
    const float* lb  = (const float*)d_in[10];
    const float* fw  = (const float*)d_in[11];
    const float* fb  = (const float*)d_in[12];
    const float* c0  = (const float*)d_in[13];
    const float* h0  = (const float*)d_in[14];
    float* out = (float*)d_out;

    float *c1, *c2, *c3, *c4, *xg, *whr;
    cudaGetSymbolAddress((void**)&c1,  g_c1);
    cudaGetSymbolAddress((void**)&c2,  g_c2);
    cudaGetSymbolAddress((void**)&c3,  g_c3);
    cudaGetSymbolAddress((void**)&c4,  g_c4);
    cudaGetSymbolAddress((void**)&xg,  g_xg);
    cudaGetSymbolAddress((void**)&whr, g_whr);

    // Wh reorder (independent of conv chain)
    reorder_wh_k<<<256, 256>>>(lw, whr);

    // conv stack — one image per block (4 for conv4), f32x2 inner loops,
    // register budget capped for >=3 resident blocks per SM.
    // conv1: 84->42, 288 thr (8cg x 6oxt(TOX7) x 6rows), grid (7, 2048)
    conv1_v3<<<dim3(7, NIMG), 288>>>(inp, w1, b1, c1);
    // conv2: 42->21, TOX=7 OXT=3 ROWS=8 IPB=1 -> 192 thr, grid (3, 2048)
    conv32_v3<42, 42, 21, 21, 0, 7, 3, 8, 1><<<dim3(3, NIMG), 192>>>(c1, w2, b2, c2);
    // conv3: 21->11, TOX=6 OXT=2 ROWS=12 IPB=1 -> 192 thr, grid (1, 2048)
    conv32_v3<21, 21, 11, 11, 1, 6, 2, 12, 1><<<dim3(1, NIMG), 192>>>(c2, w3, b3, c3);
    // conv4: 11->6,  TOX=6 OXT=1 ROWS=6 IPB=4 -> 192 thr, grid (1, 512)
    conv32_v3<11, 11,  6,  6, 1, 6, 1, 6, 4><<<dim3(1, NIMG / 4), 192>>>(c3, w4, b4, c4);

    // time-parallel part of the LSTM input GEMM (+ bias), f32x2 micro-kernel
    sgemm_xg_v2<<<dim3(8, 16), 256>>>(c4, lw, lb, xg);

    // recurrence + FC head fused, one persistent block per trajectory
    lstm_fused_v2<<<NT, HID>>>(xg, whr, fw, fb, c0, h0, out);
}

// round 8
// speedup vs baseline: 1.8306x; 1.1621x over previous
#include <cuda_runtime.h>
#include <math.h>
#include <stdint.h>
#include <string.h>

// ---------------------------------------------------------------------------
// Problem constants
//   inputs [2048, 84, 84, 4] NHWC fp32
//   conv 3x3 s2 SAME x4 (ELU), channels 4->32->32->32->32
//   84 -> 42 -> 21 -> 11 -> 6   (FEAT = 6*6*32 = 1152)
//   LSTM size 256 over TL=64 steps, NT=32 trajectories, forget_bias=1
//   FC 256 -> 18
// ---------------------------------------------------------------------------

#define NIMG   2048
#define NT     32
#define TL     64
#define FEAT   1152
#define HID    256
#define NOUT   18

typedef unsigned long long u64;

// ---------------- packed f32x2 helpers (FFMA2: PTX-only pattern) -----------
__device__ __forceinline__ u64 bcast2(float x) {
    u64 d; asm("mov.b64 %0, {%1, %1};" : "=l"(d) : "f"(x)); return d;
}
__device__ __forceinline__ u64 pack2(float a, float b) {
    u64 d; asm("mov.b64 %0, {%1, %2};" : "=l"(d) : "f"(a), "f"(b)); return d;
}
__device__ __forceinline__ float2 unpack2(u64 v) {
    float2 r; asm("mov.b64 {%0, %1}, %2;" : "=f"(r.x), "=f"(r.y) : "l"(v)); return r;
}
__device__ __forceinline__ void fma2(u64& d, u64 a, u64 b) {
    asm("fma.rn.f32x2 %0, %1, %2, %0;" : "+l"(d) : "l"(a), "l"(b));
}

__device__ __forceinline__ float elu_(float v) { return v > 0.f ? v : (__expf(v) - 1.f); }

// ------------------------- device scratch (no cudaMalloc allowed) ----------
__device__ float g_c1[(size_t)NIMG * 42 * 42 * 32];   // 462 MB
__device__ float g_c2[(size_t)NIMG * 21 * 21 * 32];   // 116 MB
__device__ float g_c3[(size_t)NIMG * 11 * 11 * 32];   //  32 MB
__device__ float g_c4[(size_t)NIMG * 6 * 6 * 32];     //   9 MB
__device__ float g_xg[(size_t)NIMG * 1024];           //   8 MB  x@Wx + b
__device__ float g_whr[HID * HID * 4];                //   1 MB  Wh interleaved

// ---------------------------------------------------------------------------
// Wh reorder: whr[(k*256 + t)*4 + g] = lstm_w[(1152+k)*1024 + g*256 + t]
// ---------------------------------------------------------------------------
__global__ void reorder_wh_k(const float* __restrict__ lw, float* __restrict__ whr)
{
    const int k = blockIdx.x;     // 0..255  (h input dim)
    const int t = threadIdx.x;    // 0..255  (hidden index)
    const float* row = lw + (size_t)(FEAT + k) * 1024;
    float4 v;
    v.x = row[t];          // i
    v.y = row[256 + t];    // j
    v.z = row[512 + t];    // f
    v.w = row[768 + t];    // o
    *(float4*)(whr + ((size_t)k * 256 + t) * 4) = v;
}

// ---------------------------------------------------------------------------
// conv1: Cin=4 -> Cout=32, 84x84 -> 42x42, pad_begin=0 (SAME pads at end).
// One image per block, 288 threads = 8 co-groups x 6 ox-tiles(TOX=7) x 6 rows.
// f32x2 accumulators over co pairs.
// ---------------------------------------------------------------------------
__global__ void __launch_bounds__(288, 2)
conv1_v3(const float* __restrict__ in, const float* __restrict__ w,
         const float* __restrict__ bias, float* __restrict__ out)
{
    __shared__ __align__(16) float sw[9 * 4 * 32];    // [kpos][ci][co]
    const int tid = threadIdx.x;
    if (tid < 288) *(float4*)(sw + tid * 4) = *(const float4*)(w + tid * 4);
    __syncthreads();

    const int cg   = tid & 7;
    const int rest = tid >> 3;
    const int oxg  = rest % 6;
    const int ry   = rest / 6;
    const int oy   = blockIdx.x * 6 + ry;             // 0..41 (7*6 exact)
    const int n    = blockIdx.y;
    const int co0  = cg * 4;
    const int ox0  = oxg * 7;                          // 6*7 = 42 exact

    u64 aL[7], aH[7];
    const u64 bL = pack2(bias[co0],     bias[co0 + 1]);
    const u64 bH = pack2(bias[co0 + 2], bias[co0 + 3]);
#pragma unroll
    for (int i = 0; i < 7; i++) { aL[i] = bL; aH[i] = bH; }

#pragma unroll 1
    for (int ky = 0; ky < 3; ky++) {
        const int iy = oy * 2 + ky;
        if (iy >= 84) continue;
        const float* inr = in + ((size_t)(n * 84 + iy) * 84) * 4;
#pragma unroll
        for (int kx = 0; kx < 3; kx++) {
            const float* swk = sw + ((ky * 3 + kx) * 4) * 32 + co0;
            const ulonglong2 w0 = *(const ulonglong2*)(swk);
            const ulonglong2 w1 = *(const ulonglong2*)(swk + 32);
            const ulonglong2 w2 = *(const ulonglong2*)(swk + 64);
            const ulonglong2 w3 = *(const ulonglong2*)(swk + 96);
#pragma unroll
            for (int i = 0; i < 7; i++) {
                const int ix = (ox0 + i) * 2 + kx;
                if (ix < 84) {
                    const float4 x = *(const float4*)(inr + (size_t)ix * 4);
                    u64 xb;
                    xb = bcast2(x.x); fma2(aL[i], xb, w0.x); fma2(aH[i], xb, w0.y);
                    xb = bcast2(x.y); fma2(aL[i], xb, w1.x); fma2(aH[i], xb, w1.y);
                    xb = bcast2(x.z); fma2(aL[i], xb, w2.x); fma2(aH[i], xb, w2.y);
                    xb = bcast2(x.w); fma2(aL[i], xb, w3.x); fma2(aH[i], xb, w3.y);
                }
            }
        }
    }
    float* outr = out + ((size_t)(n * 42 + oy) * 42) * 32 + co0;
#pragma unroll
    for (int i = 0; i < 7; i++) {
        const float2 lo = unpack2(aL[i]), hi = unpack2(aH[i]);
        float4 v;
        v.x = elu_(lo.x); v.y = elu_(lo.y); v.z = elu_(hi.x); v.w = elu_(hi.y);
        *(float4*)(outr + (size_t)(ox0 + i) * 32) = v;
    }
}

// ---------------------------------------------------------------------------
// convN: Cin=32 -> Cout=32, f32x2 over co pairs.
// block = 8 co-groups * OXT * ROWS * IPB threads; IPB images in parallel.
// launch_bounds(NTH, 2): 128-reg budget -> no spills (R7's 3-block/96-reg cap
// spilled accumulators: DRAM 32%, 1.76x slower). 12 warps/SM vs R6's 6.
// ky loop rolled to bound live ranges; kx/c4/TOX fully unrolled.
// ---------------------------------------------------------------------------
template <int IH, int IW, int OH, int OW, int PAD, int TOX, int OXT, int ROWS, int IPB>
__global__ void __launch_bounds__(8 * OXT * ROWS * IPB, 2)
conv32_v3(const float* __restrict__ in, const float* __restrict__ w,
          const float* __restrict__ bias, float* __restrict__ out)
{
    __shared__ __align__(16) float sw[9 * 32 * 32];   // [kpos][ci][co] = 36 KB
    const int tid = threadIdx.x;
    const int NTH = 8 * OXT * ROWS * IPB;
    for (int i = tid * 4; i < 9 * 32 * 32; i += NTH * 4)
        *(float4*)(sw + i) = *(const float4*)(w + i);
    __syncthreads();

    const int cg  = tid & 7;
    int rest      = tid >> 3;
    const int oxg = rest % OXT;  rest /= OXT;
    const int ry  = rest % ROWS;
    const int img = rest / ROWS;
    const int co0 = cg * 4;
    const int ox0 = oxg * TOX;
    const int oy  = blockIdx.x * ROWS + ry;
    const int n   = blockIdx.y * IPB + img;
    if (oy >= OH) return;

    u64 aL[TOX], aH[TOX];
    const u64 bL = pack2(bias[co0],     bias[co0 + 1]);
    const u64 bH = pack2(bias[co0 + 2], bias[co0 + 3]);
#pragma unroll
    for (int i = 0; i < TOX; i++) { aL[i] = bL; aH[i] = bH; }

#pragma unroll 1
    for (int ky = 0; ky < 3; ky++) {
        const int iy = oy * 2 + ky - PAD;
        if (iy < 0 || iy >= IH) continue;
        const float* inr = in + ((size_t)(n * IH + iy) * IW) * 32;
#pragma unroll
        for (int kx = 0; kx < 3; kx++) {
            const float* swk = sw + ((ky * 3 + kx) * 32) * 32 + co0;
#pragma unroll
            for (int c4 = 0; c4 < 32; c4 += 4) {
                const ulonglong2 w0 = *(const ulonglong2*)(swk + (c4 + 0) * 32);
                const ulonglong2 w1 = *(const ulonglong2*)(swk + (c4 + 1) * 32);
                const ulonglong2 w2 = *(const ulonglong2*)(swk + (c4 + 2) * 32);
                const ulonglong2 w3 = *(const ulonglong2*)(swk + (c4 + 3) * 32);
#pragma unroll
                for (int i = 0; i < TOX; i++) {
                    const int ix = (ox0 + i) * 2 + kx - PAD;
                    if (ix >= 0 && ix < IW) {
                        const float4 x = *(const float4*)(inr + (size_t)ix * 32 + c4);
                        u64 xb;
                        xb = bcast2(x.x); fma2(aL[i], xb, w0.x); fma2(aH[i], xb, w0.y);
                        xb = bcast2(x.y); fma2(aL[i], xb, w1.x); fma2(aH[i], xb, w1.y);
                        xb = bcast2(x.z); fma2(aL[i], xb, w2.x); fma2(aH[i], xb, w2.y);
                        xb = bcast2(x.w); fma2(aL[i], xb, w3.x); fma2(aH[i], xb, w3.y);
                    }
                }
            }
        }
    }
    float* outr = out + ((size_t)(n * OH + oy) * OW) * 32 + co0;
#pragma unroll
    for (int i = 0; i < TOX; i++) {
        if (ox0 + i < OW) {
            const float2 lo = unpack2(aL[i]), hi = unpack2(aH[i]);
            float4 v;
            v.x = elu_(lo.x); v.y = elu_(lo.y); v.z = elu_(hi.x); v.w = elu_(hi.y);
            *(float4*)(outr + (size_t)(ox0 + i) * 32) = v;
        }
    }
}

// ---------------------------------------------------------------------------
// SGEMM: xg[2048,1024] = c4[2048,1152] @ lstm_w[0:1152, 0:1024] + lstm_b
// 128x128x8 tiling, 256 threads, 8x8 micro-tile as f32x2 pairs over columns.
// ---------------------------------------------------------------------------
__global__ void __launch_bounds__(256, 2)
sgemm_xg_v2(const float* __restrict__ A, const float* __restrict__ B,
            const float* __restrict__ bias, float* __restrict__ C)
{
    __shared__ __align__(16) float As[8][128];
    __shared__ __align__(16) float Bs[8][128];
    const int bx  = blockIdx.x;   // 0..7   (N tiles)
    const int by  = blockIdx.y;   // 0..15  (M tiles)
    const int tid = threadIdx.x;
    const int tr  = (tid / 16) * 8;
    const int tc  = (tid % 16) * 8;

    u64 acc[8][4];
#pragma unroll
    for (int i = 0; i < 8; i++)
#pragma unroll
        for (int j = 0; j < 4; j++) acc[i][j] = 0ull;

    const int ar = tid >> 1,  ac = (tid & 1) * 4;
    const int br = tid >> 5,  bc = (tid & 31) * 4;
    const float* Aptr = A + (size_t)(by * 128 + ar) * FEAT + ac;
    const float* Bptr = B + (size_t)br * 1024 + bx * 128 + bc;

    for (int k0 = 0; k0 < FEAT; k0 += 8) {
        const float4 av = *(const float4*)(Aptr + k0);
        As[ac + 0][ar] = av.x; As[ac + 1][ar] = av.y;
        As[ac + 2][ar] = av.z; As[ac + 3][ar] = av.w;
        *(float4*)&Bs[br][bc] = *(const float4*)(Bptr + (size_t)k0 * 1024);
        __syncthreads();
#pragma unroll
        for (int kk = 0; kk < 8; kk++) {
            const float4 a0 = *(const float4*)&As[kk][tr];
            const float4 a1 = *(const float4*)&As[kk][tr + 4];
            const ulonglong2 b0 = *(const ulonglong2*)&Bs[kk][tc];
            const ulonglong2 b1 = *(const ulonglong2*)&Bs[kk][tc + 4];
            const float a[8] = {a0.x, a0.y, a0.z, a0.w, a1.x, a1.y, a1.z, a1.w};
#pragma unroll
            for (int i = 0; i < 8; i++) {
                const u64 ab = bcast2(a[i]);
                fma2(acc[i][0], ab, b0.x);
                fma2(acc[i][1], ab, b0.y);
                fma2(acc[i][2], ab, b1.x);
                fma2(acc[i][3], ab, b1.y);
            }
        }
        __syncthreads();
    }

#pragma unroll
    for (int i = 0; i < 8; i++) {
        const int row = by * 128 + tr + i;
        float* crow = C + (size_t)row * 1024 + bx * 128 + tc;
#pragma unroll
        for (int j = 0; j < 2; j++) {
            const float2 p0 = unpack2(acc[i][j * 2 + 0]);
            const float2 p1 = unpack2(acc[i][j * 2 + 1]);
            float4 v;
            v.x = p0.x + bias[bx * 128 + tc + j * 4 + 0];
            v.y = p0.y + bias[bx * 128 + tc + j * 4 + 1];
            v.z = p1.x + bias[bx * 128 + tc + j * 4 + 2];
            v.w = p1.y + bias[bx * 128 + tc + j * 4 + 3];
            *(float4*)(crow + j * 4) = v;
        }
    }
}

// ---------------------------------------------------------------------------
// Fused LSTM recurrence + FC. One persistent block per trajectory (32 blocks),
// 256 threads = hidden size. Thread t owns c[t] and accumulates gate pairs
// (i,j) and (f,o) as f32x2 with dual chains. h lives in SMEM; 18-col FC head
// runs in warps 0..5 each step, straight to d_out.
// ---------------------------------------------------------------------------
__device__ __forceinline__ float sigmoidf_(float x) { return 1.f / (1.f + expf(-x)); }

__global__ void __launch_bounds__(256)
lstm_fused_v2(const float* __restrict__ xg, const float* __restrict__ whr,
              const float* __restrict__ fcw, const float* __restrict__ fcb,
              const float* __restrict__ c0, const float* __restrict__ h0,
              float* __restrict__ out)
{
    const int n   = blockIdx.x;    // trajectory
    const int tid = threadIdx.x;   // hidden index
    __shared__ float sh[HID];

    float c = c0[(size_t)n * HID + tid];
    sh[tid] = h0[(size_t)n * HID + tid];
    __syncthreads();

    const int wrp = tid >> 5, lane = tid & 31;

    for (int t = 0; t < TL; t++) {
        const float* xrow = xg + (size_t)(n * TL + t) * 1024;
        u64 gij0 = pack2(xrow[tid],       xrow[256 + tid]), gij1 = 0ull;
        u64 gfo0 = pack2(xrow[512 + tid], xrow[768 + tid]), gfo1 = 0ull;

#pragma unroll 4
        for (int k = 0; k < HID; k += 2) {
            const u64 hb0 = bcast2(sh[k]);
            const ulonglong2 w0 = *(const ulonglong2*)(whr + ((size_t)k * HID + tid) * 4);
            fma2(gij0, hb0, w0.x); fma2(gfo0, hb0, w0.y);
            const u64 hb1 = bcast2(sh[k + 1]);
            const ulonglong2 w1 = *(const ulonglong2*)(whr + ((size_t)(k + 1) * HID + tid) * 4);
            fma2(gij1, hb1, w1.x); fma2(gfo1, hb1, w1.y);
        }
        const float2 ij0 = unpack2(gij0), ij1 = unpack2(gij1);
        const float2 fo0 = unpack2(gfo0), fo1 = unpack2(gfo1);
        const float gi = ij0.x + ij1.x, gj = ij0.y + ij1.y;
        const float gf = fo0.x + fo1.x, go = fo0.y + fo1.y;

        const float nc = c * sigmoidf_(gf + 1.f) + sigmoidf_(gi) * tanhf(gj);
        const float nh = tanhf(nc) * sigmoidf_(go);
        c = nc;

        __syncthreads();
        sh[tid] = nh;
        __syncthreads();

        // FC head: 18 columns, warps 0..5 take 3 columns each
        if (wrp < 6) {
#pragma unroll
            for (int cc = 0; cc < 3; cc++) {
                const int col = wrp * 3 + cc;
                float s = 0.f;
#pragma unroll
                for (int k = lane; k < HID; k += 32) s += sh[k] * fcw[(size_t)k * NOUT + col];
#pragma unroll
                for (int off = 16; off; off >>= 1) s += __shfl_down_sync(0xffffffffu, s, off);
                if (lane == 0)
                    out[(size_t)(n * TL + t) * NOUT + col] = s + fcb[col];
            }
        }
    }
}

// ---------------------------------------------------------------------------
// Launch
// ---------------------------------------------------------------------------
extern "C" void kernel_launch(void* const* d_in, const int* in_sizes, int n_in,
                              void* d_out, int out_size)
{
    (void)in_sizes; (void)n_in; (void)out_size;
    const float* inp = (const float*)d_in[0];
    const float* w1  = (const float*)d_in[1];
    const float* b1  = (const float*)d_in[2];
    const float* w2  = (const float*)d_in[3];
    const float* b2  = (const float*)d_in[4];
    const float* w3  = (const float*)d_in[5];
    const float* b3  = (const float*)d_in[6];
    const float* w4  = (const float*)d_in[7];
    const float* b4  = (const float*)d_in[8];
    const float* lw  = (const float*)d_in[9];
    const float* lb  = (const float*)d_in[10];
    const float* fw  = (const float*)d_in[11];
    const float* fb  = (const float*)d_in[12];
    const float* c0  = (const float*)d_in[13];
    const float* h0  = (const float*)d_in[14];
    float* out = (float*)d_out;

    float *c1, *c2, *c3, *c4, *xg, *whr;
    cudaGetSymbolAddress((void**)&c1,  g_c1);
    cudaGetSymbolAddress((void**)&c2,  g_c2);
    cudaGetSymbolAddress((void**)&c3,  g_c3);
    cudaGetSymbolAddress((void**)&c4,  g_c4);
    cudaGetSymbolAddress((void**)&xg,  g_xg);
    cudaGetSymbolAddress((void**)&whr, g_whr);

    // Wh reorder (independent of conv chain)
    reorder_wh_k<<<256, 256>>>(lw, whr);

    // conv stack — one image per block (4 for conv4), f32x2 inner loops,
    // 128-reg budget (2 blocks/SM): no spills, 12 warps/SM.
    // conv1: 84->42, 288 thr (8cg x 6oxt(TOX7) x 6rows), grid (7, 2048)
    conv1_v3<<<dim3(7, NIMG), 288>>>(inp, w1, b1, c1);
    // conv2: 42->21, TOX=7 OXT=3 ROWS=8 IPB=1 -> 192 thr, grid (3, 2048)
    conv32_v3<42, 42, 21, 21, 0, 7, 3, 8, 1><<<dim3(3, NIMG), 192>>>(c1, w2, b2, c2);
    // conv3: 21->11, TOX=6 OXT=2 ROWS=12 IPB=1 -> 192 thr, grid (1, 2048)
    conv32_v3<21, 21, 11, 11, 1, 6, 2, 12, 1><<<dim3(1, NIMG), 192>>>(c2, w3, b3, c3);
    // conv4: 11->6,  TOX=6 OXT=1 ROWS=6 IPB=4 -> 192 thr, grid (1, 512)
    conv32_v3<11, 11,  6,  6, 1, 6, 1, 6, 4><<<dim3(1, NIMG / 4), 192>>>(c3, w4, b4, c4);

    // time-parallel part of the LSTM input GEMM (+ bias), f32x2 micro-kernel
    sgemm_xg_v2<<<dim3(8, 16), 256>>>(c4, lw, lb, xg);

    // recurrence + FC head fused, one persistent block per trajectory
    lstm_fused_v2<<<NT, HID>>>(xg, whr, fw, fb, c0, h0, out);
}